// round 8
// baseline (speedup 1.0000x reference)
#include <cuda_runtime.h>
#include <cuda_fp16.h>

// GCN 2-layer + mean pool — CSR pull-mode, dinv-prescaled fp16 feature rows.
// Inputs: 0:x[100000,5] f32  1:edge_index[2,3.2M] i32  2:batch[100000] i32
//         3:W1[5,16] 4:b1[16] 5:W2[16,16] 6:b2[16]   Output: [512,16] f32
//
// Math: out_i = dinv_i * ( sum_{s->i} sfeat_s + sfeat_i ) + b, sfeat = dinv*feat.
// Feature rows stored as fp16 (32B/node) -> one L2 sector per neighbor gather.
// Cross-run invariants (graph replay): g_ecnt zeroed by k_pull1, semaphores
// reset by their own last blocks, pool/cnt zeroed by k_init_hist.

#define MAX_NODES  100000
#define MAX_EDGES  3200000
#define MAX_GRAPHS 512
#define SCAN_BLK   1024

__device__ float g_dinv[MAX_NODES];
__device__ __align__(16) float  g_feat [MAX_NODES * 16]; // fp32 xW1 (pre-scale)
__device__ __align__(16) __half g_feath[MAX_NODES * 16]; // dinv*(xW1), fp16
__device__ __align__(16) __half g_acch [MAX_NODES * 16]; // dinv*(h1@W2), fp16
__device__ float g_pool[MAX_GRAPHS * 16];
__device__ float g_cnt [MAX_GRAPHS];
__device__ int   g_ecnt  [MAX_NODES];
__device__ int   g_rowptr[MAX_NODES + 1];
__device__ int   g_pos   [MAX_NODES];
__device__ int   g_esrc  [MAX_EDGES];
__device__ int   g_bsum  [128];
__device__ int   g_boff  [128];
__device__ int   g_total;
__device__ int   g_semaA;   // static-zero, self-resetting
__device__ int   g_semaP;   // static-zero, self-resetting

// ---------------------------------------------------------------- K0: init (feat=x@W1, zero pool) + hist
__global__ void k_init_hist(const float* __restrict__ x,
                            const float* __restrict__ W1,
                            const int* __restrict__ dst,
                            int N, int G, int E, int nInitBlk) {
    if ((int)blockIdx.x < nInitBlk) {
        __shared__ float sW1[80];
        if (threadIdx.x < 80) sW1[threadIdx.x] = W1[threadIdx.x];
        __syncthreads();
        int t = blockIdx.x * 256 + threadIdx.x;
        if (t < G * 16) g_pool[t] = 0.f;
        if (t < G)      g_cnt[t]  = 0.f;
        if (t >= N * 16) return;
        int i = t >> 4, f = t & 15;
        float acc = 0.f;
#pragma unroll
        for (int k = 0; k < 5; k++)
            acc += __ldg(&x[i * 5 + k]) * sW1[k * 16 + f];
        g_feat[t] = acc;
    } else {
        int e = (blockIdx.x - nInitBlk) * 256 + threadIdx.x;
        if (e >= E) return;
        int d = dst[e];
        if ((unsigned)d < (unsigned)N) atomicAdd(&g_ecnt[d], 1);  // pre-zeroed
    }
}

// ---------------------------------------------------------------- K1: block scans + last-block sum-scan
__global__ void k_scanA(int N, int nb) {
    __shared__ int wsum[32];
    __shared__ int amLast;
    int tid = threadIdx.x;
    int i = blockIdx.x * SCAN_BLK + tid;
    int v = (i < N) ? g_ecnt[i] : 0;
    int xv = v;
#pragma unroll
    for (int o = 1; o < 32; o <<= 1) {
        int y = __shfl_up_sync(0xffffffffu, xv, o);
        if ((tid & 31) >= o) xv += y;
    }
    if ((tid & 31) == 31) wsum[tid >> 5] = xv;
    __syncthreads();
    if (tid < 32) {
        int w = wsum[tid];
#pragma unroll
        for (int o = 1; o < 32; o <<= 1) {
            int y = __shfl_up_sync(0xffffffffu, w, o);
            if (tid >= o) w += y;
        }
        wsum[tid] = w;
    }
    __syncthreads();
    int base = (tid >= 32) ? wsum[(tid >> 5) - 1] : 0;
    int incl = xv + base;
    if (i < N) g_rowptr[i] = incl - v;                 // local exclusive
    if (tid == SCAN_BLK - 1) {
        g_bsum[blockIdx.x] = incl;
        __threadfence();
        int old = atomicAdd(&g_semaA, 1);
        amLast = (old == nb - 1);
    }
    __syncthreads();
    // Last-finishing block: exclusive-scan the <=128 block sums (1 warp, 4/thread)
    if (amLast && tid < 32) {
        __threadfence();
        int vloc[4]; int s = 0;
#pragma unroll
        for (int k = 0; k < 4; k++) {
            int idx = tid * 4 + k;
            vloc[k] = (idx < nb) ? g_bsum[idx] : 0;
            s += vloc[k];
        }
        int xs = s;
#pragma unroll
        for (int o = 1; o < 32; o <<= 1) {
            int y = __shfl_up_sync(0xffffffffu, xs, o);
            if (tid >= o) xs += y;
        }
        int b = xs - s;                                // exclusive base
#pragma unroll
        for (int k = 0; k < 4; k++) { g_boff[tid * 4 + k] = b; b += vloc[k]; }
        if (tid == 31) g_total = xs;
        if (tid == 0)  g_semaA = 0;                    // reset for next run
    }
}

// ---------------------------------------------------------------- K2: finalize rowptr/dinv + fp16 prescale
__global__ void k_scanC(int N) {
    int t = blockIdx.x * 256 + threadIdx.x;
    if (t == 0) g_rowptr[N] = g_total;
    int i = t >> 2;
    if (i >= N) return;
    int lane = t & 3;
    float di = rsqrtf((float)(g_ecnt[i] + 1));         // +1 = self loop
    if (lane == 0) {
        int r = g_rowptr[i] + g_boff[i >> 10];
        g_rowptr[i] = r;
        g_pos[i]    = r;
        g_dinv[i]   = di;
    }
    float4 v = ((const float4*)g_feat)[i * 4 + lane];
    __half2 h0 = __floats2half2_rn(v.x * di, v.y * di);
    __half2 h1 = __floats2half2_rn(v.z * di, v.w * di);
    uint2 u;
    u.x = *reinterpret_cast<unsigned*>(&h0);
    u.y = *reinterpret_cast<unsigned*>(&h1);
    ((uint2*)g_feath)[i * 4 + lane] = u;
}

// ---------------------------------------------------------------- K3: scatter edges into CSR
__global__ void k_scatter(const int* __restrict__ src,
                          const int* __restrict__ dst, int E, int N) {
    int e = blockIdx.x * 256 + threadIdx.x;
    if (e >= E) return;
    int s = src[e], d = dst[e];
    if ((unsigned)s >= (unsigned)N || (unsigned)d >= (unsigned)N) return;
    int p = atomicAdd(&g_pos[d], 1);
    g_esrc[p] = s;
}

// ---------------------------------------------------------------- fp16 pull core: 4 thr/node, 8B/lane
__device__ __forceinline__ void hacc(float4& a, uint2 v) {
    __half2 h0 = *reinterpret_cast<__half2*>(&v.x);
    __half2 h1 = *reinterpret_cast<__half2*>(&v.y);
    float2 p = __half22float2(h0), q = __half22float2(h1);
    a.x += p.x; a.y += p.y; a.z += q.x; a.w += q.y;
}

__device__ __forceinline__ float4 pull_node_h(int node, int lane,
                                              const uint2* __restrict__ f) {
    int j   = g_rowptr[node];
    int end = g_rowptr[node + 1];
    float4 a0 = make_float4(0.f, 0.f, 0.f, 0.f);
    float4 a1 = make_float4(0.f, 0.f, 0.f, 0.f);
    for (; j + 8 <= end; j += 8) {
        int s0 = g_esrc[j+0], s1 = g_esrc[j+1], s2 = g_esrc[j+2], s3 = g_esrc[j+3];
        int s4 = g_esrc[j+4], s5 = g_esrc[j+5], s6 = g_esrc[j+6], s7 = g_esrc[j+7];
        uint2 v0 = f[s0*4 + lane], v1 = f[s1*4 + lane];
        uint2 v2 = f[s2*4 + lane], v3 = f[s3*4 + lane];
        uint2 v4 = f[s4*4 + lane], v5 = f[s5*4 + lane];
        uint2 v6 = f[s6*4 + lane], v7 = f[s7*4 + lane];
        hacc(a0, v0); hacc(a1, v1); hacc(a0, v2); hacc(a1, v3);
        hacc(a0, v4); hacc(a1, v5); hacc(a0, v6); hacc(a1, v7);
    }
    for (; j < end; j++) hacc(a0, f[g_esrc[j]*4 + lane]);
    hacc(a0, f[node*4 + lane]);                        // self (pre-scaled)
    float dd = g_dinv[node];
    return make_float4(dd*(a0.x + a1.x), dd*(a0.y + a1.y),
                       dd*(a0.z + a1.z), dd*(a0.w + a1.w));
}

// ---------------------------------------------------------------- K4: layer-1 pull + relu + @W2 -> fp16
__global__ void k_pull1(const float* __restrict__ b1,
                        const float* __restrict__ W2, int N) {
    __shared__ float sW2[256];
    __shared__ float sb1[16];
    if (threadIdx.x < 256) sW2[threadIdx.x] = W2[threadIdx.x];
    if (threadIdx.x < 16)  sb1[threadIdx.x] = b1[threadIdx.x];
    __syncthreads();
    int t = blockIdx.x * 256 + threadIdx.x;
    int node = t >> 2;
    bool valid = node < N;
    int nodec = valid ? node : N - 1;                  // keep shfl groups intact
    int lane = t & 3;
    float4 r = pull_node_h(nodec, lane, (const uint2*)g_feath);
    float4 h;
    h.x = fmaxf(r.x + sb1[lane*4+0], 0.f);
    h.y = fmaxf(r.y + sb1[lane*4+1], 0.f);
    h.z = fmaxf(r.z + sb1[lane*4+2], 0.f);
    h.w = fmaxf(r.w + sb1[lane*4+3], 0.f);
    float4 res = make_float4(0.f, 0.f, 0.f, 0.f);
    int fb = lane * 4;
#pragma unroll
    for (int g = 0; g < 4; g++) {
        float hx = __shfl_sync(0xffffffffu, h.x, g, 4);
        float hy = __shfl_sync(0xffffffffu, h.y, g, 4);
        float hz = __shfl_sync(0xffffffffu, h.z, g, 4);
        float hw = __shfl_sync(0xffffffffu, h.w, g, 4);
        int kb = g * 4;
        const float* w0 = &sW2[(kb+0)*16 + fb];
        const float* w1 = &sW2[(kb+1)*16 + fb];
        const float* w2 = &sW2[(kb+2)*16 + fb];
        const float* w3 = &sW2[(kb+3)*16 + fb];
        res.x += hx*w0[0] + hy*w1[0] + hz*w2[0] + hw*w3[0];
        res.y += hx*w0[1] + hy*w1[1] + hz*w2[1] + hw*w3[1];
        res.z += hx*w0[2] + hy*w1[2] + hz*w2[2] + hw*w3[2];
        res.w += hx*w0[3] + hy*w1[3] + hz*w2[3] + hw*w3[3];
    }
    if (valid) {
        float dd = g_dinv[node];                       // prescale for layer-2 pull
        __half2 h0 = __floats2half2_rn(res.x * dd, res.y * dd);
        __half2 h1 = __floats2half2_rn(res.z * dd, res.w * dd);
        uint2 u;
        u.x = *reinterpret_cast<unsigned*>(&h0);
        u.y = *reinterpret_cast<unsigned*>(&h1);
        ((uint2*)g_acch)[node*4 + lane] = u;
        if (lane == 0) g_ecnt[node] = 0;               // leave zeroed for next run
    }
}

// ---------------------------------------------------------------- K5: layer-2 pull + relu + pool + out
__global__ void k_pull2(const int* __restrict__ batch,
                        const float* __restrict__ b2,
                        float* __restrict__ out, int N, int G, int nblk) {
    __shared__ int amLast;
    int t = blockIdx.x * 256 + threadIdx.x;
    int node = t >> 2;
    int lane = t & 3;
    if (node < N) {
        float4 r  = pull_node_h(node, lane, (const uint2*)g_acch);
        float4 bv = __ldg(&((const float4*)b2)[lane]);
        float hx = fmaxf(r.x + bv.x, 0.f);
        float hy = fmaxf(r.y + bv.y, 0.f);
        float hz = fmaxf(r.z + bv.z, 0.f);
        float hw = fmaxf(r.w + bv.w, 0.f);
        int g = batch[node];
        if ((unsigned)g < (unsigned)G) {
            float* p = &g_pool[g * 16 + lane * 4];
            atomicAdd(p + 0, hx);
            atomicAdd(p + 1, hy);
            atomicAdd(p + 2, hz);
            atomicAdd(p + 3, hw);
            if (lane == 0) atomicAdd(&g_cnt[g], 1.0f);
        }
    }
    __syncthreads();
    if (threadIdx.x == 0) {
        __threadfence();
        int old = atomicAdd(&g_semaP, 1);
        amLast = (old == nblk - 1);
    }
    __syncthreads();
    if (amLast) {
        __threadfence();
        for (int u = threadIdx.x; u < G * 16; u += 256)
            out[u] = g_pool[u] / fmaxf(g_cnt[u >> 4], 1.0f);
        if (threadIdx.x == 0) g_semaP = 0;             // reset for next run
    }
}

// ----------------------------------------------------------------
extern "C" void kernel_launch(void* const* d_in, const int* in_sizes, int n_in,
                              void* d_out, int out_size) {
    const float* x     = (const float*)d_in[0];
    const int*   ei    = (const int*)d_in[1];
    const int*   batch = (const int*)d_in[2];
    const float* W1    = (const float*)d_in[3];
    const float* b1    = (const float*)d_in[4];
    const float* W2    = (const float*)d_in[5];
    const float* b2    = (const float*)d_in[6];
    float*       out   = (float*)d_out;

    int N = in_sizes[0] / 5;        // 100000
    int E = in_sizes[1] / 2;        // 3200000
    int G = out_size / 16;          // 512

    const int* src = ei;
    const int* dst = ei + E;

    int gN16 = (N * 16 + 255) / 256;
    int gE   = (E + 255) / 256;
    int gN4  = (N * 4 + 255) / 256;
    int nb   = (N + SCAN_BLK - 1) / SCAN_BLK;   // 98 (<=128)

    k_init_hist<<<gN16 + gE, 256>>>(x, W1, dst, N, G, E, gN16);
    k_scanA  <<<nb,  SCAN_BLK>>>(N, nb);
    k_scanC  <<<gN4, 256>>>(N);
    k_scatter<<<gE,  256>>>(src, dst, E, N);
    k_pull1  <<<gN4, 256>>>(b1, W2, N);
    k_pull2  <<<gN4, 256>>>(batch, b2, out, N, G, gN4);
}